// round 16
// baseline (speedup 1.0000x reference)
#include <cuda_runtime.h>
#include <math.h>

#define NPIX 16384
#define BN   65536   // 4 * 16384

// ------------ scratch ------------------------------------------------------
__device__ float g_k[64*BN];
__device__ float g_v[64*BN];
__device__ float g_q[64*BN];
__device__ float g_xm[64*BN];
__device__ float g_Gpart[4*128*1024];
__device__ float g_sqp[4*128*64];
__device__ float g_skp[4*128*64];
__device__ float g_wcat[4096];       // [c][j]
__device__ float g_wik[4096];        // (in_w@wk) [c][o]
__device__ float g_wiv[4096];        // (in_w@wv) [c][o]
__device__ float g_bcat[64];
__device__ float g_bik[64];
__device__ float g_biv[64];
// mma B-fragment buffers (tf32)
__device__ float g_w1f[8192];
__device__ float g_w2f[16384];
__device__ float g_w3f[8192];
__device__ float g_wqf[4096];
__device__ float g_wcf[4096];
__device__ float g_wkf[4096];
__device__ float g_wvf[4096];
__device__ float g_wefff[4*4096];    // per-batch Weff frags

// ------------ tf32 mma helpers -----------------------------------------------
__device__ __forceinline__ float tf32f(float x){
    unsigned u; asm("cvt.rna.tf32.f32 %0, %1;" : "=r"(u) : "f"(x));
    return __uint_as_float(u);
}
#define MMA_TF32(D, A0,A1,A2,A3, B0,B1) \
    asm volatile("mma.sync.aligned.m16n8k8.row.col.f32.tf32.tf32.f32 " \
        "{%0,%1,%2,%3},{%4,%5,%6,%7},{%8,%9},{%0,%1,%2,%3};" \
        : "+f"(D[0]),"+f"(D[1]),"+f"(D[2]),"+f"(D[3]) \
        : "r"(A0),"r"(A1),"r"(A2),"r"(A3),"r"(B0),"r"(B1))

__device__ __forceinline__ void load_afrag(unsigned a[8][4], const float* base, int st, int r0, int tid){
    const float* A0 = base + r0*st + tid;
    const float* A1 = A0 + 8*st;
    #pragma unroll
    for (int kg=0;kg<8;kg++){
        a[kg][0]=__float_as_uint(A0[kg*8]);
        a[kg][1]=__float_as_uint(A1[kg*8]);
        a[kg][2]=__float_as_uint(A0[kg*8+4]);
        a[kg][3]=__float_as_uint(A1[kg*8+4]);
    }
}
__device__ __forceinline__ void mma8(float D[8][4], const unsigned a[8][4],
                                     const float2* Bf, int nbg0, int NBT, int kgoff){
    #pragma unroll
    for (int nb=0;nb<8;nb++){
        const float2* Bp = Bf + (nbg0+nb)*32;
        #pragma unroll
        for (int kg=0;kg<8;kg++){
            float2 bf = Bp[(size_t)(kg+kgoff)*NBT*32];
            MMA_TF32(D[nb], a[kg][0],a[kg][1],a[kg][2],a[kg][3],
                     __float_as_uint(bf.x), __float_as_uint(bf.y));
        }
    }
}
__device__ __forceinline__ void mma4(float D[4][4], const unsigned a[8][4],
                                     const float2* Bf, int nbg0, int NBT, int kgoff){
    #pragma unroll
    for (int nb=0;nb<4;nb++){
        const float2* Bp = Bf + (nbg0+nb)*32;
        #pragma unroll
        for (int kg=0;kg<8;kg++){
            float2 bf = Bp[(size_t)(kg+kgoff)*NBT*32];
            MMA_TF32(D[nb], a[kg][0],a[kg][1],a[kg][2],a[kg][3],
                     __float_as_uint(bf.x), __float_as_uint(bf.y));
        }
    }
}

// ------------ kprep / kfold / kfrag -------------------------------------------
__global__ void kprep(const float* wa, const float* ba, const float* wb, const float* bb)
{
    int t = blockIdx.x*256 + threadIdx.x;
    if (t < 4096){
        int c = t>>6, j = t&63;
        float w;
        if (j < 4) w = wa[c*4 + j];
        else { int u=j-4; int kk=u/3; int d=u-kk*3; w = wb[kk*192 + c*3 + d]; }
        g_wcat[t] = w;
    }
    if (t < 64) g_bcat[t] = (t < 4) ? ba[t] : bb[t-4];
}

__global__ void kfold(const float* inw, const float* inb,
                      const float* wk, const float* bk,
                      const float* wv, const float* bv)
{
    int t = blockIdx.x*256 + threadIdx.x;
    int c = (t>>6)&63, o = t&63;
    const float* wx = (t < 4096) ? wk : wv;
    float acc = 0.f;
    #pragma unroll 4
    for (int m=0;m<64;m++) acc = fmaf(inw[c*64+m], wx[m*64+o], acc);
    if (t < 4096) g_wik[c*64+o] = acc;
    else          g_wiv[c*64+o] = acc;
    if (t < 64){
        float a=0.f, b2=0.f;
        for (int m=0;m<64;m++){ a=fmaf(inb[m],wk[m*64+t],a); b2=fmaf(inb[m],wv[m*64+t],b2); }
        g_bik[t] = a + bk[t];
        g_biv[t] = b2 + bv[t];
    }
}

__device__ __forceinline__ void make_frag(const float* w, float* f, int N, int j){
    int NBT = N>>3;
    int kg = j/(NBT*32); int rem = j - kg*(NBT*32); int nb = rem>>5; int l = rem&31;
    int gid = l>>2, tid = l&3;
    int n = nb*8+gid, k0 = kg*8+tid;
    f[2*j]   = tf32f(w[k0*N+n]);
    f[2*j+1] = tf32f(w[(k0+4)*N+n]);
}

__global__ void kfrag(const float* w1, const float* w2, const float* w3, const float* wq)
{
    int j = blockIdx.x*256 + threadIdx.x;          // 0..24575
    if      (j < 4096)  make_frag(w1,     g_w1f, 128, j);
    else if (j < 12288) make_frag(w2,     g_w2f, 128, j-4096);
    else if (j < 16384) make_frag(w3,     g_w3f,  64, j-12288);
    else if (j < 18432) make_frag(wq,     g_wqf,  64, j-16384);
    else if (j < 20480) make_frag(g_wcat, g_wcf,  64, j-18432);
    else if (j < 22528) make_frag(g_wik,  g_wkf,  64, j-20480);
    else                make_frag(g_wiv,  g_wvf,  64, j-22528);
}

// ------------ k12: merged k1 (feat->k,v) + k2 (LN-MLP->xm,q) ------------------
#define K1_ST 68
#define XS_ST 68
#define US_ST 132

__device__ void k1_body(float* smx, const float* __restrict__ x, const float* __restrict__ sem, int tile)
{
    float* Xs = smx;               // 64*68
    float* As = smx + 4352;        // 64*68
    float* Sm = smx + 8704;        // 21*64
    float* sb = smx + 10048;       // 192

    int t=threadIdx.x, lane=t&31, wrp=t>>5;
    int gid=lane>>2, tid=lane&3;
    int px0=(wrp&3)*16, oB=(wrp>>2)*32;
    int nbg0=(wrp>>2)*4;
    int r0=px0+gid, r1=r0+8;
    int gp0=tile*64;
    int b=gp0>>14, pb=gp0&(NPIX-1);
    int xbase=b*64*NPIX+pb, sbase=b*21*NPIX+pb;

    for (int i=t;i<4096;i+=256){
        int c=i>>6, px=i&63;
        Xs[px*K1_ST+c] = tf32f(x[xbase+c*NPIX+px]);
    }
    for (int i=t;i<1344;i+=256){
        int kk=i>>6, px=i&63;
        float sv=sem[sbase+kk*NPIX+px];
        Sm[kk*64+px]=sv>0.f?sv:0.f;
    }
    if (t<64){ sb[t]=g_bcat[t]; sb[64+t]=g_bik[t]; sb[128+t]=g_biv[t]; }
    __syncthreads();

    unsigned a[8][4];
    load_afrag(a, Xs, K1_ST, r0, tid);
    float D3[4][4];
    #pragma unroll
    for (int nb=0;nb<4;nb++){ D3[nb][0]=0.f; D3[nb][1]=0.f; D3[nb][2]=0.f; D3[nb][3]=0.f; }
    mma4(D3, a, ((const float2*)g_wcf)+lane, nbg0, 8, 0);
    #pragma unroll
    for (int nb=0;nb<4;nb++){
        int n0 = oB + nb*8 + 2*tid, n1 = n0+1;
        int c0 = (n0<4)?0:((n0-4)/3+1);
        int c1 = (n1<4)?0:((n1-4)/3+1);
        float b0=sb[n0], b1=sb[n1];
        *(float2*)&As[r0*K1_ST+n0] = make_float2(
            tf32f(Sm[c0*64+r0]*D3[nb][0]+b0), tf32f(Sm[c1*64+r0]*D3[nb][1]+b1));
        *(float2*)&As[r1*K1_ST+n0] = make_float2(
            tf32f(Sm[c0*64+r1]*D3[nb][2]+b0), tf32f(Sm[c1*64+r1]*D3[nb][3]+b1));
    }
    __syncthreads();

    load_afrag(a, As, K1_ST, r0, tid);
    #pragma unroll
    for (int nb=0;nb<4;nb++){ D3[nb][0]=0.f; D3[nb][1]=0.f; D3[nb][2]=0.f; D3[nb][3]=0.f; }
    mma4(D3, a, ((const float2*)g_wkf)+lane, nbg0, 8, 0);
    #pragma unroll
    for (int nb=0;nb<4;nb++){
        int n0 = oB + nb*8 + 2*tid;
        float b0=sb[64+n0], b1=sb[64+n0+1];
        *(float2*)&Xs[r0*K1_ST+n0] = make_float2(D3[nb][0]+b0, D3[nb][1]+b1);
        *(float2*)&Xs[r1*K1_ST+n0] = make_float2(D3[nb][2]+b0, D3[nb][3]+b1);
    }
    __syncthreads();
    for (int idx=t; idx<4096; idx+=256){
        int px=idx&63, o=idx>>6;
        g_k[o*BN + gp0 + px] = Xs[px*K1_ST+o];
    }

    #pragma unroll
    for (int nb=0;nb<4;nb++){ D3[nb][0]=0.f; D3[nb][1]=0.f; D3[nb][2]=0.f; D3[nb][3]=0.f; }
    mma4(D3, a, ((const float2*)g_wvf)+lane, nbg0, 8, 0);
    __syncthreads();
    #pragma unroll
    for (int nb=0;nb<4;nb++){
        int n0 = oB + nb*8 + 2*tid;
        float b0=sb[128+n0], b1=sb[128+n0+1];
        *(float2*)&Xs[r0*K1_ST+n0] = make_float2(D3[nb][0]+b0, D3[nb][1]+b1);
        *(float2*)&Xs[r1*K1_ST+n0] = make_float2(D3[nb][2]+b0, D3[nb][3]+b1);
    }
    __syncthreads();
    for (int idx=t; idx<4096; idx+=256){
        int px=idx&63, o=idx>>6;
        g_v[o*BN + gp0 + px] = Xs[px*K1_ST+o];
    }
}

__device__ void k2_body(float* smx, const float* __restrict__ x,
   const float* __restrict__ b1, const float* __restrict__ gm1, const float* __restrict__ be1,
   const float* __restrict__ b2, const float* __restrict__ gm2, const float* __restrict__ be2,
   const float* __restrict__ b3, const float* __restrict__ bq, int tile)
{
    float* Xs  = smx;            // 64x68  = 4352
    float* Us  = smx + 4352;     // 64x132 = 8448
    float* s_p = smx + 12800;    // 896
    float* SSs = smx + 13696;    // 128
    float* SSq = smx + 13824;    // 128

    int t = threadIdx.x, lane = t&31, wrp = t>>5;
    int gid = lane>>2, tid = lane&3;
    int px0 = (wrp&3)*16, oA = (wrp>>2)*64, oB = (wrp>>2)*32, hh = wrp>>2;
    int nbg8 = hh*8, nbg4 = hh*4;
    int r0 = px0+gid, r1 = r0+8;
    int gp0 = tile*64;
    int b = gp0>>14, pb = gp0 & (NPIX-1);
    int xbase = b*64*NPIX + pb;

    if (t<128){ s_p[t]=b1[t]; s_p[128+t]=gm1[t]; s_p[256+t]=be1[t];
                s_p[384+t]=b2[t]; s_p[512+t]=gm2[t]; s_p[640+t]=be2[t]; }
    if (t<64){ s_p[768+t]=b3[t]; s_p[832+t]=bq[t]; }
    for (int i=t;i<4096;i+=256){
        int c=i>>6, px=i&63;
        Xs[px*XS_ST+c] = tf32f(x[xbase + c*NPIX + px]);
    }
    __syncthreads();

    // GEMM1
    float D[8][4];
    #pragma unroll
    for (int nb=0;nb<8;nb++){ D[nb][0]=0.f; D[nb][1]=0.f; D[nb][2]=0.f; D[nb][3]=0.f; }
    {
        unsigned a[8][4];
        load_afrag(a, Xs, XS_ST, r0, tid);
        mma8(D, a, ((const float2*)g_w1f)+lane, nbg8, 16, 0);
    }
    {
        float s0=0.f,s1=0.f,q0=0.f,q1=0.f;
        #pragma unroll
        for (int nb=0;nb<8;nb++){
            int n0 = oA + nb*8 + 2*tid;
            float bb0=s_p[n0], bb1=s_p[n0+1];
            D[nb][0]+=bb0; D[nb][1]+=bb1; D[nb][2]+=bb0; D[nb][3]+=bb1;
            s0+=D[nb][0]+D[nb][1]; q0=fmaf(D[nb][0],D[nb][0],q0); q0=fmaf(D[nb][1],D[nb][1],q0);
            s1+=D[nb][2]+D[nb][3]; q1=fmaf(D[nb][2],D[nb][2],q1); q1=fmaf(D[nb][3],D[nb][3],q1);
        }
        s0+=__shfl_xor_sync(0xffffffffu,s0,1); s0+=__shfl_xor_sync(0xffffffffu,s0,2);
        s1+=__shfl_xor_sync(0xffffffffu,s1,1); s1+=__shfl_xor_sync(0xffffffffu,s1,2);
        q0+=__shfl_xor_sync(0xffffffffu,q0,1); q0+=__shfl_xor_sync(0xffffffffu,q0,2);
        q1+=__shfl_xor_sync(0xffffffffu,q1,1); q1+=__shfl_xor_sync(0xffffffffu,q1,2);
        if (tid==0){ SSs[hh*64+r0]=s0; SSs[hh*64+r1]=s1; SSq[hh*64+r0]=q0; SSq[hh*64+r1]=q1; }
    }
    __syncthreads();
    {
        float m0=(SSs[r0]+SSs[64+r0])*(1.f/128.f);
        float m1=(SSs[r1]+SSs[64+r1])*(1.f/128.f);
        float ri0=rsqrtf((SSq[r0]+SSq[64+r0])*(1.f/128.f)-m0*m0+1e-5f);
        float ri1=rsqrtf((SSq[r1]+SSq[64+r1])*(1.f/128.f)-m1*m1+1e-5f);
        #pragma unroll
        for (int nb=0;nb<8;nb++){
            int n0 = oA + nb*8 + 2*tid;
            float g0=s_p[128+n0], g1=s_p[128+n0+1], e0=s_p[256+n0], e1=s_p[256+n0+1];
            float h00=(D[nb][0]-m0)*ri0*g0+e0; h00=h00>0.f?h00:0.01f*h00;
            float h01=(D[nb][1]-m0)*ri0*g1+e1; h01=h01>0.f?h01:0.01f*h01;
            float h10=(D[nb][2]-m1)*ri1*g0+e0; h10=h10>0.f?h10:0.01f*h10;
            float h11=(D[nb][3]-m1)*ri1*g1+e1; h11=h11>0.f?h11:0.01f*h11;
            *(float2*)&Us[r0*US_ST+n0] = make_float2(tf32f(h00), tf32f(h01));
            *(float2*)&Us[r1*US_ST+n0] = make_float2(tf32f(h10), tf32f(h11));
        }
    }
    __syncthreads();

    // GEMM2
    #pragma unroll
    for (int nb=0;nb<8;nb++){ D[nb][0]=0.f; D[nb][1]=0.f; D[nb][2]=0.f; D[nb][3]=0.f; }
    {
        unsigned a[8][4];
        load_afrag(a, Us, US_ST, r0, tid);
        mma8(D, a, ((const float2*)g_w2f)+lane, nbg8, 16, 0);
        load_afrag(a, Us+64, US_ST, r0, tid);
        mma8(D, a, ((const float2*)g_w2f)+lane, nbg8, 16, 8);
    }
    {
        float s0=0.f,s1=0.f,q0=0.f,q1=0.f;
        #pragma unroll
        for (int nb=0;nb<8;nb++){
            int n0 = oA + nb*8 + 2*tid;
            float bb0=s_p[384+n0], bb1=s_p[384+n0+1];
            D[nb][0]+=bb0; D[nb][1]+=bb1; D[nb][2]+=bb0; D[nb][3]+=bb1;
            s0+=D[nb][0]+D[nb][1]; q0=fmaf(D[nb][0],D[nb][0],q0); q0=fmaf(D[nb][1],D[nb][1],q0);
            s1+=D[nb][2]+D[nb][3]; q1=fmaf(D[nb][2],D[nb][2],q1); q1=fmaf(D[nb][3],D[nb][3],q1);
        }
        s0+=__shfl_xor_sync(0xffffffffu,s0,1); s0+=__shfl_xor_sync(0xffffffffu,s0,2);
        s1+=__shfl_xor_sync(0xffffffffu,s1,1); s1+=__shfl_xor_sync(0xffffffffu,s1,2);
        q0+=__shfl_xor_sync(0xffffffffu,q0,1); q0+=__shfl_xor_sync(0xffffffffu,q0,2);
        q1+=__shfl_xor_sync(0xffffffffu,q1,1); q1+=__shfl_xor_sync(0xffffffffu,q1,2);
        if (tid==0){ SSs[hh*64+r0]=s0; SSs[hh*64+r1]=s1; SSq[hh*64+r0]=q0; SSq[hh*64+r1]=q1; }
    }
    __syncthreads();
    {
        float m0=(SSs[r0]+SSs[64+r0])*(1.f/128.f);
        float m1=(SSs[r1]+SSs[64+r1])*(1.f/128.f);
        float ri0=rsqrtf((SSq[r0]+SSq[64+r0])*(1.f/128.f)-m0*m0+1e-5f);
        float ri1=rsqrtf((SSq[r1]+SSq[64+r1])*(1.f/128.f)-m1*m1+1e-5f);
        #pragma unroll
        for (int nb=0;nb<8;nb++){
            int n0 = oA + nb*8 + 2*tid;
            float g0=s_p[512+n0], g1=s_p[512+n0+1], e0=s_p[640+n0], e1=s_p[640+n0+1];
            float h00=(D[nb][0]-m0)*ri0*g0+e0; h00=h00>0.f?h00:0.01f*h00;
            float h01=(D[nb][1]-m0)*ri0*g1+e1; h01=h01>0.f?h01:0.01f*h01;
            float h10=(D[nb][2]-m1)*ri1*g0+e0; h10=h10>0.f?h10:0.01f*h10;
            float h11=(D[nb][3]-m1)*ri1*g1+e1; h11=h11>0.f?h11:0.01f*h11;
            *(float2*)&Us[r0*US_ST+n0] = make_float2(tf32f(h00), tf32f(h01));
            *(float2*)&Us[r1*US_ST+n0] = make_float2(tf32f(h10), tf32f(h11));
        }
    }
    __syncthreads();

    // GEMM3
    float D3[4][4];
    #pragma unroll
    for (int nb=0;nb<4;nb++){ D3[nb][0]=0.f; D3[nb][1]=0.f; D3[nb][2]=0.f; D3[nb][3]=0.f; }
    {
        unsigned a[8][4];
        load_afrag(a, Us, US_ST, r0, tid);
        mma4(D3, a, ((const float2*)g_w3f)+lane, nbg4, 8, 0);
        load_afrag(a, Us+64, US_ST, r0, tid);
        mma4(D3, a, ((const float2*)g_w3f)+lane, nbg4, 8, 8);
    }
    #pragma unroll
    for (int nb=0;nb<4;nb++){
        int n0 = oB + nb*8 + 2*tid;
        float bb0=s_p[768+n0], bb1=s_p[768+n0+1];
        *(float2*)&Xs[r0*XS_ST+n0] = make_float2(D3[nb][0]+bb0, D3[nb][1]+bb1);
        *(float2*)&Xs[r1*XS_ST+n0] = make_float2(D3[nb][2]+bb0, D3[nb][3]+bb1);
    }
    __syncthreads();
    for (int idx=t; idx<4096; idx+=256){
        int px=idx&63, o=idx>>6;
        float v = Xs[px*XS_ST+o];
        g_xm[o*BN + gp0 + px] = v;
        Us[px*US_ST+o] = tf32f(v);
    }
    __syncthreads();

    // q-GEMM
    #pragma unroll
    for (int nb=0;nb<4;nb++){ D3[nb][0]=0.f; D3[nb][1]=0.f; D3[nb][2]=0.f; D3[nb][3]=0.f; }
    {
        unsigned a[8][4];
        load_afrag(a, Us, US_ST, r0, tid);
        mma4(D3, a, ((const float2*)g_wqf)+lane, nbg4, 8, 0);
    }
    #pragma unroll
    for (int nb=0;nb<4;nb++){
        int n0 = oB + nb*8 + 2*tid;
        float bb0=s_p[832+n0], bb1=s_p[832+n0+1];
        *(float2*)&Xs[r0*XS_ST+n0] = make_float2(D3[nb][0]+bb0, D3[nb][1]+bb1);
        *(float2*)&Xs[r1*XS_ST+n0] = make_float2(D3[nb][2]+bb0, D3[nb][3]+bb1);
    }
    __syncthreads();
    for (int idx=t; idx<4096; idx+=256){
        int px=idx&63, o=idx>>6;
        g_q[o*BN + gp0 + px] = Xs[px*XS_ST+o];
    }
}

__global__ void __launch_bounds__(256,2)
k12(const float* __restrict__ x, const float* __restrict__ sem,
    const float* __restrict__ b1, const float* __restrict__ gm1, const float* __restrict__ be1,
    const float* __restrict__ b2, const float* __restrict__ gm2, const float* __restrict__ be2,
    const float* __restrict__ b3, const float* __restrict__ bq)
{
    extern __shared__ float smx[];
    int tile = blockIdx.x >> 1;
    if (blockIdx.x & 1)
        k1_body(smx, x, sem, tile);
    else
        k2_body(smx, x, b1,gm1,be1, b2,gm2,be2, b3,bq, tile);
}

// ------------ k3: Gram + norm partials per 128-pixel chunk -------------------
#define CHUNK 128
#define TP 129
__global__ void __launch_bounds__(256,2) k3()
{
    extern __shared__ float smx[];
    float* qs  = smx;
    float* ks  = smx + 64*TP;
    float* red = smx + 128*TP;
    int t = threadIdx.x;
    int chunk = blockIdx.x, b = blockIdx.y;
    int pbase = b*NPIX + chunk*CHUNK;
    for (int i=t; i<64*CHUNK; i+=256){
        int ch=i>>7, pp=i&(CHUNK-1);
        qs[ch*TP+pp]=g_q[ch*BN+pbase+pp];
        ks[ch*TP+pp]=g_k[ch*BN+pbase+pp];
    }
    __syncthreads();
    int sub=t>>6, combo=t&63;
    int h=combo>>4, d4=(combo>>2)&3, e4=combo&3;
    const float* qsb=qs+(h*16+d4*4)*TP;
    const float* ksb=ks+(h*16+e4*4)*TP;
    float acc[4][4];
    #pragma unroll
    for (int i=0;i<4;i++)
        #pragma unroll
        for (int j=0;j<4;j++) acc[i][j]=0.f;
    for (int pp=sub*32; pp<sub*32+32; pp++){
        float q0=qsb[pp],q1=qsb[TP+pp],q2=qsb[2*TP+pp],q3=qsb[3*TP+pp];
        float k0=ksb[pp],k1v=ksb[TP+pp],k2v=ksb[2*TP+pp],k3v=ksb[3*TP+pp];
        acc[0][0]=fmaf(q0,k0,acc[0][0]); acc[0][1]=fmaf(q0,k1v,acc[0][1]); acc[0][2]=fmaf(q0,k2v,acc[0][2]); acc[0][3]=fmaf(q0,k3v,acc[0][3]);
        acc[1][0]=fmaf(q1,k0,acc[1][0]); acc[1][1]=fmaf(q1,k1v,acc[1][1]); acc[1][2]=fmaf(q1,k2v,acc[1][2]); acc[1][3]=fmaf(q1,k3v,acc[1][3]);
        acc[2][0]=fmaf(q2,k0,acc[2][0]); acc[2][1]=fmaf(q2,k1v,acc[2][1]); acc[2][2]=fmaf(q2,k2v,acc[2][2]); acc[2][3]=fmaf(q2,k3v,acc[2][3]);
        acc[3][0]=fmaf(q3,k0,acc[3][0]); acc[3][1]=fmaf(q3,k1v,acc[3][1]); acc[3][2]=fmaf(q3,k2v,acc[3][2]); acc[3][3]=fmaf(q3,k3v,acc[3][3]);
    }
    #pragma unroll
    for (int i=0;i<4;i++)
        #pragma unroll
        for (int j=0;j<4;j++)
            red[sub*1024 + (h*16+d4*4+i)*16 + (e4*4+j)] = acc[i][j];
    if (t < 64){
        const float* qr=qs+t*TP;
        float a0=0,a1=0,a2=0,a3=0;
        for (int pp=0;pp<CHUNK;pp+=4){
            a0=fmaf(qr[pp+0],qr[pp+0],a0); a1=fmaf(qr[pp+1],qr[pp+1],a1);
            a2=fmaf(qr[pp+2],qr[pp+2],a2); a3=fmaf(qr[pp+3],qr[pp+3],a3);
        }
        g_sqp[(b*128+chunk)*64+t]=(a0+a1)+(a2+a3);
    } else if (t < 128){
        int ch=t-64;
        const float* kr=ks+ch*TP;
        float a0=0,a1=0,a2=0,a3=0;
        for (int pp=0;pp<CHUNK;pp+=4){
            a0=fmaf(kr[pp+0],kr[pp+0],a0); a1=fmaf(kr[pp+1],kr[pp+1],a1);
            a2=fmaf(kr[pp+2],kr[pp+2],a2); a3=fmaf(kr[pp+3],kr[pp+3],a3);
        }
        g_skp[(b*128+chunk)*64+ch]=(a0+a1)+(a2+a3);
    }
    __syncthreads();
    float* gout = g_Gpart + (b*128+chunk)*1024;
    for (int idx=t; idx<1024; idx+=256)
        gout[idx] = (red[idx]+red[1024+idx]) + (red[2048+idx]+red[3072+idx]);
}

// ------------ k4: reduce + softmax + fold A into wo -> Weff frags -------------
__global__ void k4(const float* __restrict__ rescale, const float* __restrict__ wo)
{
    __shared__ float sG[1024];
    __shared__ float snq[64], snk[64];
    __shared__ float sA[1024];
    __shared__ float swo[4096];
    __shared__ float sW[4096];
    int b=blockIdx.x, t=threadIdx.x;
    {
        float a0=0.f,a1=0.f,a2=0.f,a3=0.f;
        for (int c=0;c<128;c++){
            const float4 v = ((const float4*)(g_Gpart+(b*128+c)*1024))[t];
            a0+=v.x; a1+=v.y; a2+=v.z; a3+=v.w;
        }
        sG[t*4+0]=a0; sG[t*4+1]=a1; sG[t*4+2]=a2; sG[t*4+3]=a3;
    }
    if (t<64){
        float aq=0.f, ak=0.f;
        for (int c=0;c<128;c++){ aq+=g_sqp[(b*128+c)*64+t]; ak+=g_skp[(b*128+c)*64+t]; }
        snq[t]=sqrtf(aq)+1e-8f; snk[t]=sqrtf(ak)+1e-8f;
    }
    for (int i=t;i<4096;i+=256) swo[i]=wo[i];
    __syncthreads();
    if (t<64){
        int h=t>>4;
        float r=rescale[h], nq=snq[t];
        float ev[16]; float mx=-1e30f;
        #pragma unroll
        for (int e=0;e<16;e++){ ev[e]=sG[t*16+e]/(nq*snk[h*16+e])*r; mx=fmaxf(mx,ev[e]); }
        float ss=0.f;
        #pragma unroll
        for (int e=0;e<16;e++){ ev[e]=expf(ev[e]-mx); ss+=ev[e]; }
        float inv=1.f/ss;
        #pragma unroll
        for (int e=0;e<16;e++) sA[t*16+e]=ev[e]*inv;
    }
    __syncthreads();
    // Weff[e][cp] = sum_d A[h(e)][d][e15] * wo[h*16+d][cp]
    for (int idx=t; idx<4096; idx+=256){
        int cp=idx>>6, e=idx&63, h=e>>4, e15=e&15;
        float acc=0.f;
        #pragma unroll
        for (int d=0;d<16;d++)
            acc = fmaf(sA[h*256 + d*16 + e15], swo[(h*16+d)*64 + cp], acc);
        sW[e*64 + cp] = acc;
    }
    __syncthreads();
    // build mma B-frags (K=64 rows=e, N=64 cols=cp)
    for (int j=t; j<2048; j+=256){
        int kg=j>>8, rem=j&255, nb=rem>>5, l=rem&31;
        int gid=l>>2, tid2=l&3;
        int n=nb*8+gid, k0=kg*8+tid2;
        g_wefff[b*4096 + 2*j]   = tf32f(sW[k0*64+n]);
        g_wefff[b*4096 + 2*j+1] = tf32f(sW[(k0+4)*64+n]);
    }
}

// ------------ k5: out = v @ Weff + bo + xm (tf32 mma) --------------------------
#define K5_ST 68
__global__ void __launch_bounds__(256,3)
k5(const float* __restrict__ bo, float* __restrict__ out)
{
    extern __shared__ float smx[];
    float* Vs  = smx;          // 64*68
    float* Os  = smx + 4352;   // 64*68
    float* sbo = smx + 8704;   // 64

    int t=threadIdx.x, lane=t&31, wrp=t>>5;
    int gid=lane>>2, tid=lane&3;
    int px0=(wrp&3)*16, oB=(wrp>>2)*32, nbg0=(wrp>>2)*4;
    int r0=px0+gid, r1=r0+8;
    int gp0=blockIdx.x*64;
    int b=gp0>>14, pb=gp0&(NPIX-1);

    for (int i=t;i<4096;i+=256){
        int e=i>>6, px=i&63;
        Vs[px*K5_ST+e] = tf32f(g_v[e*BN + gp0 + px]);
    }
    if (t<64) sbo[t]=bo[t];
    __syncthreads();

    unsigned a[8][4];
    load_afrag(a, Vs, K5_ST, r0, tid);
    float D3[4][4];
    #pragma unroll
    for (int nb=0;nb<4;nb++){ D3[nb][0]=0.f; D3[nb][1]=0.f; D3[nb][2]=0.f; D3[nb][3]=0.f; }
    mma4(D3, a, ((const float2*)(g_wefff + b*4096))+lane, nbg0, 8, 0);
    #pragma unroll
    for (int nb=0;nb<4;nb++){
        int n0 = oB + nb*8 + 2*tid;
        float b0=sbo[n0], b1=sbo[n0+1];
        *(float2*)&Os[r0*K5_ST+n0] = make_float2(D3[nb][0]+b0, D3[nb][1]+b1);
        *(float2*)&Os[r1*K5_ST+n0] = make_float2(D3[nb][2]+b0, D3[nb][3]+b1);
    }
    __syncthreads();
    for (int idx=t; idx<4096; idx+=256){
        int px=idx&63, o=idx>>6;
        out[(size_t)(b*64+o)*NPIX + pb + px] = Os[px*K5_ST+o] + g_xm[o*BN + gp0 + px];
    }
}

// ------------ launch ----------------------------------------------------------
extern "C" void kernel_launch(void* const* d_in, const int* in_sizes, int n_in,
                              void* d_out, int out_size)
{
    const float* x   =(const float*)d_in[0];
    const float* sem =(const float*)d_in[1];
    const float* wa  =(const float*)d_in[2];
    const float* ba  =(const float*)d_in[3];
    const float* wb  =(const float*)d_in[4];
    const float* bb  =(const float*)d_in[5];
    const float* inw =(const float*)d_in[6];
    const float* inb =(const float*)d_in[7];
    const float* w1  =(const float*)d_in[8];
    const float* b1  =(const float*)d_in[9];
    const float* gm1 =(const float*)d_in[10];
    const float* be1 =(const float*)d_in[11];
    const float* w2  =(const float*)d_in[12];
    const float* b2  =(const float*)d_in[13];
    const float* gm2 =(const float*)d_in[14];
    const float* be2 =(const float*)d_in[15];
    const float* w3  =(const float*)d_in[16];
    const float* b3  =(const float*)d_in[17];
    const float* wq  =(const float*)d_in[18];
    const float* bq  =(const float*)d_in[19];
    const float* wk  =(const float*)d_in[20];
    const float* bk  =(const float*)d_in[21];
    const float* wv  =(const float*)d_in[22];
    const float* bv  =(const float*)d_in[23];
    const float* wo  =(const float*)d_in[24];
    const float* bo  =(const float*)d_in[25];
    const float* rescale=(const float*)d_in[26];
    float* out=(float*)d_out;

    cudaFuncSetAttribute(k12, cudaFuncAttributeMaxDynamicSharedMemorySize, 13952*4);
    cudaFuncSetAttribute(k3,  cudaFuncAttributeMaxDynamicSharedMemorySize, (128*TP+4096)*4);
    cudaFuncSetAttribute(k5,  cudaFuncAttributeMaxDynamicSharedMemorySize, 8768*4);

    kprep<<<16,256>>>(wa,ba,wb,bb);
    kfold<<<32,256>>>(inw,inb,wk,bk,wv,bv);
    kfrag<<<96,256>>>(w1,w2,w3,wq);
    k12<<<2048,256,13952*4>>>(x,sem,b1,gm1,be1,b2,gm2,be2,b3,bq);
    k3<<<dim3(128,4),256,(128*TP+4096)*4>>>();
    k4<<<4,256>>>(rescale,wo);
    k5<<<1024,256,8768*4>>>(bo,out);
}

// round 17
// speedup vs baseline: 1.0656x; 1.0656x over previous
#include <cuda_runtime.h>
#include <math.h>

#define NPIX 16384
#define BN   65536   // 4 * 16384

typedef unsigned long long u64;

// ------------ scratch ------------------------------------------------------
__device__ float g_k[64*BN];
__device__ float g_v[64*BN];
__device__ float g_q[64*BN];
__device__ float g_xm[64*BN];
__device__ float g_Gpart[4*128*1024];
__device__ float g_sqp[4*128*64];
__device__ float g_skp[4*128*64];
__device__ float g_weff[4*4096];     // [b][e*64+cp]
__device__ float g_wcat[4096];       // [c][j]
__device__ float g_wik[4096];        // (in_w@wk) [c][o]
__device__ float g_wiv[4096];        // (in_w@wv) [c][o]
__device__ float g_bcat[64];
__device__ float g_bik[64];
__device__ float g_biv[64];
// mma B-fragment buffers (tf32)
__device__ float g_w1f[8192];
__device__ float g_w2f[16384];
__device__ float g_w3f[8192];
__device__ float g_wqf[4096];
__device__ float g_wcf[4096];
__device__ float g_wkf[4096];
__device__ float g_wvf[4096];

// ------------ f32x2 helpers (k5) ---------------------------------------------
__device__ __forceinline__ u64 pack2(float lo, float hi){
    u64 r; asm("mov.b64 %0, {%1,%2};" : "=l"(r) : "f"(lo), "f"(hi)); return r;
}
__device__ __forceinline__ void unpack2(u64 a, float& lo, float& hi){
    asm("mov.b64 {%0,%1}, %2;" : "=f"(lo), "=f"(hi) : "l"(a));
}
__device__ __forceinline__ u64 fma2_(u64 a, u64 b, u64 c){
    u64 d; asm("fma.rn.f32x2 %0, %1, %2, %3;" : "=l"(d) : "l"(a), "l"(b), "l"(c)); return d;
}
__device__ __forceinline__ u64 add2_(u64 a, u64 b){
    u64 d; asm("add.rn.f32x2 %0, %1, %2;" : "=l"(d) : "l"(a), "l"(b)); return d;
}
__device__ __forceinline__ int SWP(int o, int p){
    return (p & 3) | ((((p >> 2) ^ (o >> 2)) & 7) << 2);
}

#define GSTEP64(W, R, RROW, KK) do{ \
    const float2 _wv = *(const float2*)((W)+(KK)*64+2*lane); \
    int _g = (((wrp)^((RROW)>>2))&7)<<2; \
    const ulonglong2 _xa = *(const ulonglong2*)((R)+(RROW)*32+_g); \
    const ulonglong2 _xb = *(const ulonglong2*)((R)+(RROW)*32+_g+2); \
    u64 _w0=pack2(_wv.x,_wv.x), _w1=pack2(_wv.y,_wv.y); \
    acc2[0][0]=fma2_(_xa.x,_w0,acc2[0][0]); acc2[0][1]=fma2_(_xa.y,_w0,acc2[0][1]); acc2[0][2]=fma2_(_xb.x,_w0,acc2[0][2]); acc2[0][3]=fma2_(_xb.y,_w0,acc2[0][3]); \
    acc2[1][0]=fma2_(_xa.x,_w1,acc2[1][0]); acc2[1][1]=fma2_(_xa.y,_w1,acc2[1][1]); acc2[1][2]=fma2_(_xb.x,_w1,acc2[1][2]); acc2[1][3]=fma2_(_xb.y,_w1,acc2[1][3]); \
}while(0)

// ------------ tf32 mma helpers -----------------------------------------------
__device__ __forceinline__ float tf32f(float x){
    unsigned u; asm("cvt.rna.tf32.f32 %0, %1;" : "=r"(u) : "f"(x));
    return __uint_as_float(u);
}
#define MMA_TF32(D, A0,A1,A2,A3, B0,B1) \
    asm volatile("mma.sync.aligned.m16n8k8.row.col.f32.tf32.tf32.f32 " \
        "{%0,%1,%2,%3},{%4,%5,%6,%7},{%8,%9},{%0,%1,%2,%3};" \
        : "+f"(D[0]),"+f"(D[1]),"+f"(D[2]),"+f"(D[3]) \
        : "r"(A0),"r"(A1),"r"(A2),"r"(A3),"r"(B0),"r"(B1))

__device__ __forceinline__ void load_afrag(unsigned a[8][4], const float* base, int st, int r0, int tid){
    const float* A0 = base + r0*st + tid;
    const float* A1 = A0 + 8*st;
    #pragma unroll
    for (int kg=0;kg<8;kg++){
        a[kg][0]=__float_as_uint(A0[kg*8]);
        a[kg][1]=__float_as_uint(A1[kg*8]);
        a[kg][2]=__float_as_uint(A0[kg*8+4]);
        a[kg][3]=__float_as_uint(A1[kg*8+4]);
    }
}
__device__ __forceinline__ void load_afrag4(unsigned a[4][4], const float* base, int st, int r0, int tid, int kg0){
    const float* A0 = base + r0*st + tid + kg0*8;
    const float* A1 = A0 + 8*st;
    #pragma unroll
    for (int kg=0;kg<4;kg++){
        a[kg][0]=__float_as_uint(A0[kg*8]);
        a[kg][1]=__float_as_uint(A1[kg*8]);
        a[kg][2]=__float_as_uint(A0[kg*8+4]);
        a[kg][3]=__float_as_uint(A1[kg*8+4]);
    }
}
__device__ __forceinline__ void mma4(float D[4][4], const unsigned a[8][4],
                                     const float2* Bf, int nbg0, int NBT, int kgoff){
    #pragma unroll
    for (int nb=0;nb<4;nb++){
        const float2* Bp = Bf + (nbg0+nb)*32;
        #pragma unroll
        for (int kg=0;kg<8;kg++){
            float2 bf = Bp[(size_t)(kg+kgoff)*NBT*32];
            MMA_TF32(D[nb], a[kg][0],a[kg][1],a[kg][2],a[kg][3],
                     __float_as_uint(bf.x), __float_as_uint(bf.y));
        }
    }
}
__device__ __forceinline__ void mma8_4(float D[8][4], const unsigned a[4][4],
                                       const float2* Bf, int nbg0, int NBT, int kgoff){
    #pragma unroll
    for (int nb=0;nb<8;nb++){
        const float2* Bp = Bf + (nbg0+nb)*32;
        #pragma unroll
        for (int kg=0;kg<4;kg++){
            float2 bf = Bp[(size_t)(kg+kgoff)*NBT*32];
            MMA_TF32(D[nb], a[kg][0],a[kg][1],a[kg][2],a[kg][3],
                     __float_as_uint(bf.x), __float_as_uint(bf.y));
        }
    }
}
__device__ __forceinline__ void mma4_4(float D[4][4], const unsigned a[4][4],
                                       const float2* Bf, int nbg0, int NBT, int kgoff){
    #pragma unroll
    for (int nb=0;nb<4;nb++){
        const float2* Bp = Bf + (nbg0+nb)*32;
        #pragma unroll
        for (int kg=0;kg<4;kg++){
            float2 bf = Bp[(size_t)(kg+kgoff)*NBT*32];
            MMA_TF32(D[nb], a[kg][0],a[kg][1],a[kg][2],a[kg][3],
                     __float_as_uint(bf.x), __float_as_uint(bf.y));
        }
    }
}

// ------------ kprep / kfold / kfrag -------------------------------------------
__global__ void kprep(const float* wa, const float* ba, const float* wb, const float* bb)
{
    int t = blockIdx.x*256 + threadIdx.x;
    if (t < 4096){
        int c = t>>6, j = t&63;
        float w;
        if (j < 4) w = wa[c*4 + j];
        else { int u=j-4; int kk=u/3; int d=u-kk*3; w = wb[kk*192 + c*3 + d]; }
        g_wcat[t] = w;
    }
    if (t < 64) g_bcat[t] = (t < 4) ? ba[t] : bb[t-4];
}

__global__ void kfold(const float* inw, const float* inb,
                      const float* wk, const float* bk,
                      const float* wv, const float* bv)
{
    int t = blockIdx.x*256 + threadIdx.x;
    int c = (t>>6)&63, o = t&63;
    const float* wx = (t < 4096) ? wk : wv;
    float acc = 0.f;
    #pragma unroll 4
    for (int m=0;m<64;m++) acc = fmaf(inw[c*64+m], wx[m*64+o], acc);
    if (t < 4096) g_wik[c*64+o] = acc;
    else          g_wiv[c*64+o] = acc;
    if (t < 64){
        float a=0.f, b2=0.f;
        for (int m=0;m<64;m++){ a=fmaf(inb[m],wk[m*64+t],a); b2=fmaf(inb[m],wv[m*64+t],b2); }
        g_bik[t] = a + bk[t];
        g_biv[t] = b2 + bv[t];
    }
}

__device__ __forceinline__ void make_frag(const float* w, float* f, int N, int j){
    int NBT = N>>3;
    int kg = j/(NBT*32); int rem = j - kg*(NBT*32); int nb = rem>>5; int l = rem&31;
    int gid = l>>2, tid = l&3;
    int n = nb*8+gid, k0 = kg*8+tid;
    f[2*j]   = tf32f(w[k0*N+n]);
    f[2*j+1] = tf32f(w[(k0+4)*N+n]);
}

__global__ void kfrag(const float* w1, const float* w2, const float* w3, const float* wq)
{
    int j = blockIdx.x*256 + threadIdx.x;          // 0..24575
    if      (j < 4096)  make_frag(w1,     g_w1f, 128, j);
    else if (j < 12288) make_frag(w2,     g_w2f, 128, j-4096);
    else if (j < 16384) make_frag(w3,     g_w3f,  64, j-12288);
    else if (j < 18432) make_frag(wq,     g_wqf,  64, j-16384);
    else if (j < 20480) make_frag(g_wcat, g_wcf,  64, j-18432);
    else if (j < 22528) make_frag(g_wik,  g_wkf,  64, j-20480);
    else                make_frag(g_wiv,  g_wvf,  64, j-22528);
}

// ------------ k1: tf32 feat path -> k, v (frag weights, 3 CTA/SM) -------------
#define K1_ST 68
__global__ void __launch_bounds__(256,3)
k1(const float* __restrict__ x, const float* __restrict__ sem)
{
    extern __shared__ float smx[];
    float* Xs = smx;               // 64*68
    float* As = smx + 4352;        // 64*68
    float* Sm = smx + 8704;        // 21*64
    float* sb = smx + 10048;       // 192

    int t=threadIdx.x, lane=t&31, wrp=t>>5;
    int gid=lane>>2, tid=lane&3;
    int px0=(wrp&3)*16, oB=(wrp>>2)*32;
    int nbg0=(wrp>>2)*4;
    int r0=px0+gid, r1=r0+8;
    int gp0=blockIdx.x*64;
    int b=gp0>>14, pb=gp0&(NPIX-1);
    int xbase=b*64*NPIX+pb, sbase=b*21*NPIX+pb;

    for (int i=t;i<4096;i+=256){
        int c=i>>6, px=i&63;
        Xs[px*K1_ST+c] = tf32f(x[xbase+c*NPIX+px]);
    }
    for (int i=t;i<1344;i+=256){
        int kk=i>>6, px=i&63;
        float sv=sem[sbase+kk*NPIX+px];
        Sm[kk*64+px]=sv>0.f?sv:0.f;
    }
    if (t<64){ sb[t]=g_bcat[t]; sb[64+t]=g_bik[t]; sb[128+t]=g_biv[t]; }
    __syncthreads();

    // ---- cat-GEMM ----
    unsigned a[8][4];
    load_afrag(a, Xs, K1_ST, r0, tid);
    float D3[4][4];
    #pragma unroll
    for (int nb=0;nb<4;nb++){ D3[nb][0]=0.f; D3[nb][1]=0.f; D3[nb][2]=0.f; D3[nb][3]=0.f; }
    mma4(D3, a, ((const float2*)g_wcf)+lane, nbg0, 8, 0);
    #pragma unroll
    for (int nb=0;nb<4;nb++){
        int n0 = oB + nb*8 + 2*tid, n1 = n0+1;
        int c0 = (n0<4)?0:((n0-4)/3+1);
        int c1 = (n1<4)?0:((n1-4)/3+1);
        float b0=sb[n0], b1=sb[n1];
        *(float2*)&As[r0*K1_ST+n0] = make_float2(
            tf32f(Sm[c0*64+r0]*D3[nb][0]+b0), tf32f(Sm[c1*64+r0]*D3[nb][1]+b1));
        *(float2*)&As[r1*K1_ST+n0] = make_float2(
            tf32f(Sm[c0*64+r1]*D3[nb][2]+b0), tf32f(Sm[c1*64+r1]*D3[nb][3]+b1));
    }
    __syncthreads();

    // ---- k-GEMM ----
    load_afrag(a, As, K1_ST, r0, tid);
    #pragma unroll
    for (int nb=0;nb<4;nb++){ D3[nb][0]=0.f; D3[nb][1]=0.f; D3[nb][2]=0.f; D3[nb][3]=0.f; }
    mma4(D3, a, ((const float2*)g_wkf)+lane, nbg0, 8, 0);
    #pragma unroll
    for (int nb=0;nb<4;nb++){
        int n0 = oB + nb*8 + 2*tid;
        float b0=sb[64+n0], b1=sb[64+n0+1];
        *(float2*)&Xs[r0*K1_ST+n0] = make_float2(D3[nb][0]+b0, D3[nb][1]+b1);
        *(float2*)&Xs[r1*K1_ST+n0] = make_float2(D3[nb][2]+b0, D3[nb][3]+b1);
    }
    __syncthreads();
    for (int idx=t; idx<4096; idx+=256){
        int px=idx&63, o=idx>>6;
        g_k[o*BN + gp0 + px] = Xs[px*K1_ST+o];
    }

    // ---- v-GEMM ----
    #pragma unroll
    for (int nb=0;nb<4;nb++){ D3[nb][0]=0.f; D3[nb][1]=0.f; D3[nb][2]=0.f; D3[nb][3]=0.f; }
    mma4(D3, a, ((const float2*)g_wvf)+lane, nbg0, 8, 0);
    __syncthreads();
    #pragma unroll
    for (int nb=0;nb<4;nb++){
        int n0 = oB + nb*8 + 2*tid;
        float b0=sb[128+n0], b1=sb[128+n0+1];
        *(float2*)&Xs[r0*K1_ST+n0] = make_float2(D3[nb][0]+b0, D3[nb][1]+b1);
        *(float2*)&Xs[r1*K1_ST+n0] = make_float2(D3[nb][2]+b0, D3[nb][3]+b1);
    }
    __syncthreads();
    for (int idx=t; idx<4096; idx+=256){
        int px=idx&63, o=idx>>6;
        g_v[o*BN + gp0 + px] = Xs[px*K1_ST+o];
    }
}

// ------------ k2: tf32 LN-MLP (split a-frags, 3 CTA/SM) ------------------------
#define XS_ST 68
#define US_ST 132

__global__ void __launch_bounds__(256,3)
k2(const float* __restrict__ x,
   const float* __restrict__ b1, const float* __restrict__ gm1, const float* __restrict__ be1,
   const float* __restrict__ b2, const float* __restrict__ gm2, const float* __restrict__ be2,
   const float* __restrict__ b3, const float* __restrict__ bq)
{
    extern __shared__ float smx[];
    float* Xs  = smx;            // 64x68  = 4352
    float* Us  = smx + 4352;     // 64x132 = 8448
    float* s_p = smx + 12800;    // 896
    float* SSs = smx + 13696;    // 128
    float* SSq = smx + 13824;    // 128

    int t = threadIdx.x, lane = t&31, wrp = t>>5;
    int gid = lane>>2, tid = lane&3;
    int px0 = (wrp&3)*16, oA = (wrp>>2)*64, oB = (wrp>>2)*32, hh = wrp>>2;
    int nbg8 = hh*8, nbg4 = hh*4;
    int r0 = px0+gid, r1 = r0+8;
    int gp0 = blockIdx.x*64;
    int b = gp0>>14, pb = gp0 & (NPIX-1);
    int xbase = b*64*NPIX + pb;

    if (t<128){ s_p[t]=b1[t]; s_p[128+t]=gm1[t]; s_p[256+t]=be1[t];
                s_p[384+t]=b2[t]; s_p[512+t]=gm2[t]; s_p[640+t]=be2[t]; }
    if (t<64){ s_p[768+t]=b3[t]; s_p[832+t]=bq[t]; }
    for (int i=t;i<4096;i+=256){
        int c=i>>6, px=i&63;
        Xs[px*XS_ST+c] = tf32f(x[xbase + c*NPIX + px]);
    }
    __syncthreads();

    // ---- GEMM1: u1 = x @ w1 + b1 ----
    float D[8][4];
    #pragma unroll
    for (int nb=0;nb<8;nb++){ D[nb][0]=0.f; D[nb][1]=0.f; D[nb][2]=0.f; D[nb][3]=0.f; }
    {
        unsigned a4[4][4];
        load_afrag4(a4, Xs, XS_ST, r0, tid, 0);
        mma8_4(D, a4, ((const float2*)g_w1f)+lane, nbg8, 16, 0);
        load_afrag4(a4, Xs, XS_ST, r0, tid, 4);
        mma8_4(D, a4, ((const float2*)g_w1f)+lane, nbg8, 16, 4);
    }
    {
        float s0=0.f,s1=0.f,q0=0.f,q1=0.f;
        #pragma unroll
        for (int nb=0;nb<8;nb++){
            int n0 = oA + nb*8 + 2*tid;
            float bb0=s_p[n0], bb1=s_p[n0+1];
            D[nb][0]+=bb0; D[nb][1]+=bb1; D[nb][2]+=bb0; D[nb][3]+=bb1;
            s0+=D[nb][0]+D[nb][1]; q0=fmaf(D[nb][0],D[nb][0],q0); q0=fmaf(D[nb][1],D[nb][1],q0);
            s1+=D[nb][2]+D[nb][3]; q1=fmaf(D[nb][2],D[nb][2],q1); q1=fmaf(D[nb][3],D[nb][3],q1);
        }
        s0+=__shfl_xor_sync(0xffffffffu,s0,1); s0+=__shfl_xor_sync(0xffffffffu,s0,2);
        s1+=__shfl_xor_sync(0xffffffffu,s1,1); s1+=__shfl_xor_sync(0xffffffffu,s1,2);
        q0+=__shfl_xor_sync(0xffffffffu,q0,1); q0+=__shfl_xor_sync(0xffffffffu,q0,2);
        q1+=__shfl_xor_sync(0xffffffffu,q1,1); q1+=__shfl_xor_sync(0xffffffffu,q1,2);
        if (tid==0){ SSs[hh*64+r0]=s0; SSs[hh*64+r1]=s1; SSq[hh*64+r0]=q0; SSq[hh*64+r1]=q1; }
    }
    __syncthreads();
    {
        float m0=(SSs[r0]+SSs[64+r0])*(1.f/128.f);
        float m1=(SSs[r1]+SSs[64+r1])*(1.f/128.f);
        float ri0=rsqrtf((SSq[r0]+SSq[64+r0])*(1.f/128.f)-m0*m0+1e-5f);
        float ri1=rsqrtf((SSq[r1]+SSq[64+r1])*(1.f/128.f)-m1*m1+1e-5f);
        #pragma unroll
        for (int nb=0;nb<8;nb++){
            int n0 = oA + nb*8 + 2*tid;
            float g0=s_p[128+n0], g1=s_p[128+n0+1], e0=s_p[256+n0], e1=s_p[256+n0+1];
            float h00=(D[nb][0]-m0)*ri0*g0+e0; h00=h00>0.f?h00:0.01f*h00;
            float h01=(D[nb][1]-m0)*ri0*g1+e1; h01=h01>0.f?h01:0.01f*h01;
            float h10=(D[nb][2]-m1)*ri1*g0+e0; h10=h10>0.f?h10:0.01f*h10;
            float h11=(D[nb][3]-m1)*ri1*g1+e1; h11=h11>0.f?h11:0.01f*h11;
            *(float2*)&Us[r0*US_ST+n0] = make_float2(tf32f(h00), tf32f(h01));
            *(float2*)&Us[r1*US_ST+n0] = make_float2(tf32f(h10), tf32f(h11));
        }
    }
    __syncthreads();

    // ---- GEMM2: u2 = h1 @ w2 + b2 (K=128, 4 a-frag quarters) ----
    #pragma unroll
    for (int nb=0;nb<8;nb++){ D[nb][0]=0.f; D[nb][1]=0.f; D[nb][2]=0.f; D[nb][3]=0.f; }
    {
        unsigned a4[4][4];
        load_afrag4(a4, Us, US_ST, r0, tid, 0);
        mma8_4(D, a4, ((const float2*)g_w2f)+lane, nbg8, 16, 0);
        load_afrag4(a4, Us, US_ST, r0, tid, 4);
        mma8_4(D, a4, ((const float2*)g_w2f)+lane, nbg8, 16, 4);
        load_afrag4(a4, Us+64, US_ST, r0, tid, 0);
        mma8_4(D, a4, ((const float2*)g_w2f)+lane, nbg8, 16, 8);
        load_afrag4(a4, Us+64, US_ST, r0, tid, 4);
        mma8_4(D, a4, ((const float2*)g_w2f)+lane, nbg8, 16, 12);
    }
    {
        float s0=0.f,s1=0.f,q0=0.f,q1=0.f;
        #pragma unroll
        for (int nb=0;nb<8;nb++){
            int n0 = oA + nb*8 + 2*tid;
            float bb0=s_p[384+n0], bb1=s_p[384+n0+1];
            D[nb][0]+=bb0; D[nb][1]+=bb1; D[nb][2]+=bb0; D[nb][3]+=bb1;
            s0+=D[nb][0]+D[nb][1]; q0=fmaf(D[nb][0],D[nb][0],q0); q0=fmaf(D[nb][1],D[nb][1],q0);
            s1+=D[nb][2]+D[nb][3]; q1=fmaf(D[nb][2],D[nb][2],q1); q1=fmaf(D[nb][3],D[nb][3],q1);
        }
        s0+=__shfl_xor_sync(0xffffffffu,s0,1); s0+=__shfl_xor_sync(0xffffffffu,s0,2);
        s1+=__shfl_xor_sync(0xffffffffu,s1,1); s1+=__shfl_xor_sync(0xffffffffu,s1,2);
        q0+=__shfl_xor_sync(0xffffffffu,q0,1); q0+=__shfl_xor_sync(0xffffffffu,q0,2);
        q1+=__shfl_xor_sync(0xffffffffu,q1,1); q1+=__shfl_xor_sync(0xffffffffu,q1,2);
        if (tid==0){ SSs[hh*64+r0]=s0; SSs[hh*64+r1]=s1; SSq[hh*64+r0]=q0; SSq[hh*64+r1]=q1; }
    }
    __syncthreads();
    {
        float m0=(SSs[r0]+SSs[64+r0])*(1.f/128.f);
        float m1=(SSs[r1]+SSs[64+r1])*(1.f/128.f);
        float ri0=rsqrtf((SSq[r0]+SSq[64+r0])*(1.f/128.f)-m0*m0+1e-5f);
        float ri1=rsqrtf((SSq[r1]+SSq[64+r1])*(1.f/128.f)-m1*m1+1e-5f);
        #pragma unroll
        for (int nb=0;nb<8;nb++){
            int n0 = oA + nb*8 + 2*tid;
            float g0=s_p[512+n0], g1=s_p[512+n0+1], e0=s_p[640+n0], e1=s_p[640+n0+1];
            float h00=(D[nb][0]-m0)*ri0*g0+e0; h00=h00>0.f?h00:0.01f*h00;
            float h01=(D[nb][1]-m0)*ri0*g1+e1; h01=h01>0.f?h01:0.01f*h01;
            float h10=(D[nb][2]-m1)*ri1*g0+e0; h10=h10>0.f?h10:0.01f*h10;
            float h11=(D[nb][3]-m1)*ri1*g1+e1; h11=h11>0.f?h11:0.01f*h11;
            *(float2*)&Us[r0*US_ST+n0] = make_float2(tf32f(h00), tf32f(h01));
            *(float2*)&Us[r1*US_ST+n0] = make_float2(tf32f(h10), tf32f(h11));
        }
    }
    __syncthreads();

    // ---- GEMM3: xm = h2 @ w3 + b3 ----
    float D3[4][4];
    #pragma unroll
    for (int nb=0;nb<4;nb++){ D3[nb][0]=0.f; D3[nb][1]=0.f; D3[nb][2]=0.f; D3[nb][3]=0.f; }
    {
        unsigned a4[4][4];
        load_afrag4(a4, Us, US_ST, r0, tid, 0);
        mma4_4(D3, a4, ((const float2*)g_w3f)+lane, nbg4, 8, 0);
        load_afrag4(a4, Us, US_ST, r0, tid, 4);
        mma4_4(D3, a4, ((const float2*)g_w3f)+lane, nbg4, 8, 4);
        load_afrag4(a4, Us+64, US_ST, r0, tid, 0);
        mma4_4(D3, a4, ((const float2*)g_w3f)+lane, nbg4, 8, 8);
        load_afrag4(a4, Us+64, US_ST, r0, tid, 4);
        mma4_4(D3, a4, ((const float2*)g_w3f)+lane, nbg4, 8, 12);
    }
    #pragma unroll
    for (int nb=0;nb<4;nb++){
        int n0 = oB + nb*8 + 2*tid;
        float bb0=s_p[768+n0], bb1=s_p[768+n0+1];
        *(float2*)&Xs[r0*XS_ST+n0] = make_float2(D3[nb][0]+bb0, D3[nb][1]+bb1);
        *(float2*)&Xs[r1*XS_ST+n0] = make_float2(D3[nb][2]+bb0, D3[nb][3]+bb1);
    }
    __syncthreads();
    for (int idx=t; idx<4096; idx+=256){
        int px=idx&63, o=idx>>6;
        float v = Xs[px*XS_ST+o];
        g_xm[o*BN + gp0 + px] = v;
        Us[px*US_ST+o] = tf32f(v);
    }
    __syncthreads();

    // ---- q-GEMM ----
    #pragma unroll
    for (int nb=0;nb<4;nb++){ D3[nb][0]=0.f; D3[nb][1]=0.f; D3[nb][2]=0.f; D3[nb][3]=0.f; }
    {
        unsigned a4[4][4];
        load_afrag4(a4, Us, US_ST, r0, tid, 0);
        mma4_4(D3, a4, ((const float2*)g_wqf)+lane, nbg4, 8, 0);
        load_afrag4(a4, Us, US_ST, r0, tid, 4);
        mma4_4(D3, a4, ((const float2*)g_wqf)+lane, nbg4, 8, 4);
    }
    #pragma unroll
    for (int nb=0;nb<4;nb++){
        int n0 = oB + nb*8 + 2*tid;
        float bb0=s_p[832+n0], bb1=s_p[832+n0+1];
        *(float2*)&Xs[r0*XS_ST+n0] = make_float2(D3[nb][0]+bb0, D3[nb][1]+bb1);
        *(float2*)&Xs[r1*XS_ST+n0] = make_float2(D3[nb][2]+bb0, D3[nb][3]+bb1);
    }
    __syncthreads();
    for (int idx=t; idx<4096; idx+=256){
        int px=idx&63, o=idx>>6;
        g_q[o*BN + gp0 + px] = Xs[px*XS_ST+o];
    }
}

// ------------ k3: Gram + norm partials per 128-pixel chunk -------------------
#define CHUNK 128
#define TP 129
__global__ void __launch_bounds__(256,2) k3()
{
    extern __shared__ float smx[];
    float* qs  = smx;
    float* ks  = smx + 64*TP;
    float* red = smx + 128*TP;
    int t = threadIdx.x;
    int chunk = blockIdx.x, b = blockIdx.y;
    int pbase = b*NPIX + chunk*CHUNK;
    for (int i=t; i<64*CHUNK; i+=256){
        int ch=i>>7, pp=i&(CHUNK-1);
        qs[ch*TP+pp]=g_q[ch*BN+pbase+pp];
        ks[ch*TP+pp]=g_k[ch*BN+pbase+pp];
    }
    __syncthreads();
    int sub=t>>6, combo=t&63;
    int h=combo>>4, d4=(combo>>2)&3, e4=combo&3;
    const float* qsb=qs+(h*16+d4*4)*TP;
    const float* ksb=ks+(h*16+e4*4)*TP;
    float acc[4][4];
    #pragma unroll
    for (int i=0;i<4;i++)
        #pragma unroll
        for (int j=0;j<4;j++) acc[i][j]=0.f;
    for (int pp=sub*32; pp<sub*32+32; pp++){
        float q0=qsb[pp],q1=qsb[TP+pp],q2=qsb[2*TP+pp],q3=qsb[3*TP+pp];
        float k0=ksb[pp],k1v=ksb[TP+pp],k2v=ksb[2*TP+pp],k3v=ksb[3*TP+pp];
        acc[0][0]=fmaf(q0,k0,acc[0][0]); acc[0][1]=fmaf(q0,k1v,acc[0][1]); acc[0][2]=fmaf(q0,k2v,acc[0][2]); acc[0][3]=fmaf(q0,k3v,acc[0][3]);
        acc[1][0]=fmaf(q1,k0,acc[1][0]); acc[1][1]=fmaf(q1,k1v,acc[1][1]); acc[1][2]=fmaf(q1,k2v,acc[1][2]); acc[1][3]=fmaf(q1,k3v,acc[1][3]);
        acc[2][0]=fmaf(q2,k0,acc[2][0]); acc[2][1]=fmaf(q2,k1v,acc[2][1]); acc[2][2]=fmaf(q2,k2v,acc[2][2]); acc[2][3]=fmaf(q2,k3v,acc[2][3]);
        acc[3][0]=fmaf(q3,k0,acc[3][0]); acc[3][1]=fmaf(q3,k1v,acc[3][1]); acc[3][2]=fmaf(q3,k2v,acc[3][2]); acc[3][3]=fmaf(q3,k3v,acc[3][3]);
    }
    #pragma unroll
    for (int i=0;i<4;i++)
        #pragma unroll
        for (int j=0;j<4;j++)
            red[sub*1024 + (h*16+d4*4+i)*16 + (e4*4+j)] = acc[i][j];
    if (t < 64){
        const float* qr=qs+t*TP;
        float a0=0,a1=0,a2=0,a3=0;
        for (int pp=0;pp<CHUNK;pp+=4){
            a0=fmaf(qr[pp+0],qr[pp+0],a0); a1=fmaf(qr[pp+1],qr[pp+1],a1);
            a2=fmaf(qr[pp+2],qr[pp+2],a2); a3=fmaf(qr[pp+3],qr[pp+3],a3);
        }
        g_sqp[(b*128+chunk)*64+t]=(a0+a1)+(a2+a3);
    } else if (t < 128){
        int ch=t-64;
        const float* kr=ks+ch*TP;
        float a0=0,a1=0,a2=0,a3=0;
        for (int pp=0;pp<CHUNK;pp+=4){
            a0=fmaf(kr[pp+0],kr[pp+0],a0); a1=fmaf(kr[pp+1],kr[pp+1],a1);
            a2=fmaf(kr[pp+2],kr[pp+2],a2); a3=fmaf(kr[pp+3],kr[pp+3],a3);
        }
        g_skp[(b*128+chunk)*64+ch]=(a0+a1)+(a2+a3);
    }
    __syncthreads();
    float* gout = g_Gpart + (b*128+chunk)*1024;
    for (int idx=t; idx<1024; idx+=256)
        gout[idx] = (red[idx]+red[1024+idx]) + (red[2048+idx]+red[3072+idx]);
}

// ------------ k4: reduce + softmax + fold A into wo --------------------------
__global__ void k4(const float* __restrict__ rescale, const float* __restrict__ wo)
{
    __shared__ float sG[1024];
    __shared__ float snq[64], snk[64];
    __shared__ float sA[1024];
    __shared__ float swo[4096];
    int b=blockIdx.x, t=threadIdx.x;
    {
        float a0=0.f,a1=0.f,a2=0.f,a3=0.f;
        for (int c=0;c<128;c++){
            const float4 v = ((const float4*)(g_Gpart+(b*128+c)*1024))[t];
            a0+=v.x; a1+=v.y; a2+=v.z; a3+=v.w;
        }
        sG[t*4+0]=a0; sG[t*4+1]=a1; sG[t*4+2]=a2; sG[t*4+3]=a3;
    }
    if (t<64){
        float aq=0.f, ak=0.f;
        for (int c=0;c<128;c++){ aq+=g_sqp[(b*128+c)*64+t]; ak+=g_skp[(b*128+c)*64+t]; }
        snq[t]=sqrtf(aq)+1e-8f; snk[t]=sqrtf(ak)+1e-8f;
    }
    for (int i=t;i<4096;i+=256) swo[i]=wo[i];
    __syncthreads();
    if (t<64){
        int h=t>>4;
        float r=rescale[h], nq=snq[t];
        float ev[16]; float mx=-1e30f;
        #pragma unroll
        for (int e=0;e<16;e++){ ev[e]=sG[t*16+e]/(nq*snk[h*16+e])*r; mx=fmaxf(mx,ev[e]); }
        float ss=0.f;
        #pragma unroll
        for (int e=0;e<16;e++){ ev[e]=expf(ev[e]-mx); ss+=ev[e]; }
        float inv=1.f/ss;
        #pragma unroll
        for (int e=0;e<16;e++) sA[t*16+e]=ev[e]*inv;
    }
    __syncthreads();
    for (int idx=t; idx<4096; idx+=256){
        int cp=idx>>6, e=idx&63, h=e>>4, e15=e&15;
        float acc=0.f;
        #pragma unroll
        for (int d=0;d<16;d++)
            acc = fmaf(sA[h*256 + d*16 + e15], swo[(h*16+d)*64 + cp], acc);
        g_weff[b*4096 + e*64 + cp] = acc;
    }
}

// ------------ k5: out = v @ Weff + bo + xm (R15 champion) ----------------------
__global__ void __launch_bounds__(256,4)
k5(const float* __restrict__ bo, float* __restrict__ out)
{
    extern __shared__ float smx[];
    float* s_w = smx;
    u64*   R1  = (u64*)(smx + 4096);
    u64*   R2  = (u64*)(smx + 8192);
    float* sbo = smx + 12288;

    int t = threadIdx.x, lane = t & 31, wrp = t >> 5;
    int gp0 = blockIdx.x*64;
    int b = gp0 >> 14, pb = gp0 & (NPIX-1);

    for (int i=t;i<4096;i+=256) s_w[i]=g_weff[b*4096+i];
    if (t<64) sbo[t]=bo[t];
    for (int i=t;i<2048;i+=256){
        int e=i>>5, pr=i&31;
        R1[e*32 + SWP(e,pr)] = pack2(g_v[e*BN + gp0 + pr], g_v[e*BN + gp0 + 32 + pr]);
    }
    __syncthreads();

    u64 acc2[2][4];
    #pragma unroll
    for (int j=0;j<2;j++){ acc2[j][0]=0ull; acc2[j][1]=0ull; acc2[j][2]=0ull; acc2[j][3]=0ull; }
    #pragma unroll 8
    for (int k=0;k<64;k++) GSTEP64(s_w, R1, k, k);
    {
        int _g = ((wrp ^ (lane>>1)) & 7) << 2;
        #pragma unroll
        for (int j=0;j<2;j++){
            int o = 2*lane+j;
            #pragma unroll
            for (int p=0;p<4;p++) R2[o*32 + _g + p] = acc2[j][p];
        }
    }
    __syncthreads();
    for (int idx=t; idx<2048; idx+=256){
        int o=idx>>5, pr=idx&31;
        float lo,hi; unpack2(R2[o*32+SWP(o,pr)], lo, hi);
        size_t row = (size_t)(b*64+o)*NPIX;
        out[row + pb + pr]      = lo + sbo[o] + g_xm[o*BN + gp0 + pr];
        out[row + pb + 32 + pr] = hi + sbo[o] + g_xm[o*BN + gp0 + 32 + pr];
    }
}

// ------------ launch ----------------------------------------------------------
extern "C" void kernel_launch(void* const* d_in, const int* in_sizes, int n_in,
                              void* d_out, int out_size)
{
    const float* x   =(const float*)d_in[0];
    const float* sem =(const float*)d_in[1];
    const float* wa  =(const float*)d_in[2];
    const float* ba  =(const float*)d_in[3];
    const float* wb  =(const float*)d_in[4];
    const float* bb  =(const float*)d_in[5];
    const float* inw =(const float*)d_in[6];
    const float* inb =(const float*)d_in[7];
    const float* w1  =(const float*)d_in[8];
    const float* b1  =(const float*)d_in[9];
    const float* gm1 =(const float*)d_in[10];
    const float* be1 =(const float*)d_in[11];
    const float* w2  =(const float*)d_in[12];
    const float* b2  =(const float*)d_in[13];
    const float* gm2 =(const float*)d_in[14];
    const float* be2 =(const float*)d_in[15];
    const float* w3  =(const float*)d_in[16];
    const float* b3  =(const float*)d_in[17];
    const float* wq  =(const float*)d_in[18];
    const float* bq  =(const float*)d_in[19];
    const float* wk  =(const float*)d_in[20];
    const float* bk  =(const float*)d_in[21];
    const float* wv  =(const float*)d_in[22];
    const float* bv  =(const float*)d_in[23];
    const float* wo  =(const float*)d_in[24];
    const float* bo  =(const float*)d_in[25];
    const float* rescale=(const float*)d_in[26];
    float* out=(float*)d_out;

    cudaFuncSetAttribute(k1, cudaFuncAttributeMaxDynamicSharedMemorySize, 10240*4);
    cudaFuncSetAttribute(k2, cudaFuncAttributeMaxDynamicSharedMemorySize, 13952*4);
    cudaFuncSetAttribute(k3, cudaFuncAttributeMaxDynamicSharedMemorySize, (128*TP+4096)*4);
    cudaFuncSetAttribute(k5, cudaFuncAttributeMaxDynamicSharedMemorySize, 12352*4);

    kprep<<<16,256>>>(wa,ba,wb,bb);
    kfold<<<32,256>>>(inw,inb,wk,bk,wv,bv);
    kfrag<<<96,256>>>(w1,w2,w3,wq);
    k1<<<1024,256,10240*4>>>(x,sem);
    k2<<<1024,256,13952*4>>>(x,b1,gm1,be1,b2,gm2,be2,b3,bq);
    k3<<<dim3(128,4),256,(128*TP+4096)*4>>>();
    k4<<<4,256>>>(rescale,wo);
    k5<<<1024,256,12352*4>>>(bo,out);
}